// round 2
// baseline (speedup 1.0000x reference)
#include <cuda_runtime.h>
#include <cstdint>

// Problem constants (fixed by the reference)
static constexpr int B  = 2048;   // batch
static constexpr int U  = 256;    // units
static constexpr int P  = 256;    // features
static constexpr int G  = 64;     // groups
static constexpr int UT = 16;     // unit tile per CTA

#define SOFTPLUS_C 0.5413248546129181f

// Scratch (allocation-free rule: __device__ globals)
__device__ int g_items[B];        // batch indices sorted by group
__device__ int g_start[G + 1];    // group offsets into g_items

__device__ __forceinline__ float softplus_f(float v) {
    // numerically stable: max(v,0) + log1p(exp(-|v|)) (matches jax.nn.softplus f32)
    return fmaxf(v, 0.0f) + log1pf(expf(-fabsf(v)));
}

// ---- cp.async helpers (Ampere+ LDGSTS path; in-flight bytes live in SMEM) ----
__device__ __forceinline__ void cp_async16(uint32_t dst_smem, const void* src) {
    asm volatile("cp.async.cg.shared.global [%0], [%1], 16;\n"
                 :: "r"(dst_smem), "l"(src));
}
__device__ __forceinline__ void cp_commit() {
    asm volatile("cp.async.commit_group;\n");
}
template <int N>
__device__ __forceinline__ void cp_wait() {
    asm volatile("cp.async.wait_group %0;\n" :: "n"(N));
}

// ---------------------------------------------------------------------------
// Kernel 1: counting-sort batches by group (single block, tiny)
// ---------------------------------------------------------------------------
__global__ void bin_kernel(const int* __restrict__ gid) {
    __shared__ int cnt[G];
    __shared__ int off[G];
    int tid = threadIdx.x;
    if (tid < G) cnt[tid] = 0;
    __syncthreads();
    for (int b = tid; b < B; b += blockDim.x)
        atomicAdd(&cnt[gid[b]], 1);
    __syncthreads();
    if (tid == 0) {
        int s = 0;
        for (int g = 0; g < G; g++) {
            g_start[g] = s;
            off[g] = s;
            s += cnt[g];
        }
        g_start[G] = s;
    }
    __syncthreads();
    for (int b = tid; b < B; b += blockDim.x) {
        int g = gid[b];
        int pos = atomicAdd(&off[g], 1);
        g_items[pos] = b;   // intra-group order nondeterministic; outputs are
                            // per-batch independent -> results deterministic
    }
}

// ---------------------------------------------------------------------------
// Kernel 2: main streaming kernel with cp.async double-buffered eps pipeline.
// grid = (U/UT, G). CTA (ux, g) owns units [u0, u0+16) of group g.
//  - weight slabs (w_mu + fused softplus(C+w_sigma)) live in SMEM, read once
//  - per batch, the 16KB eps tile (16 contiguous unit rows) is bulk-fetched
//    via cp.async.cg into a 2-stage ring; compute consumes the previous tile
//  - warp owns 2 units; interleaved shuffle reductions
// Dynamic SMEM: wmu 16KB | sp 16KB | eps 2x16KB = 64KB  -> 3 CTAs/SM
// ---------------------------------------------------------------------------
__global__ __launch_bounds__(256) void multilevel_dense_kernel(
    const float* __restrict__ x,
    const float* __restrict__ w_mu,
    const float* __restrict__ w_sigma,
    const float* __restrict__ b_mu,
    const float* __restrict__ b_sigma,
    const float* __restrict__ eps_w,
    const float* __restrict__ eps_b,
    float* __restrict__ out)
{
    extern __shared__ float smem[];
    float* s_wmu = smem;            // 4096 floats
    float* s_sp  = smem + 4096;     // 4096 floats
    float* s_eps = smem + 8192;     // 2 * 4096 floats

    const int g    = blockIdx.y;
    const int u0   = blockIdx.x * UT;
    const int tid  = threadIdx.x;
    const int warp = tid >> 5;
    const int lane = tid & 31;

    const int start = g_start[g];
    const int end   = g_start[g + 1];

    const uint32_t s_eps_addr = (uint32_t)__cvta_generic_to_shared(s_eps);

    // ---- prologue: start eps fetch for the first batch ASAP (overlaps slab load)
    if (start < end) {
        const int b = g_items[start];
        const float4* src = reinterpret_cast<const float4*>(eps_w + ((size_t)b * U + u0) * P);
        #pragma unroll
        for (int i = tid; i < UT * P / 4; i += 256)
            cp_async16(s_eps_addr + i * 16, src + i);
    }
    cp_commit();

    // ---- weight slab load with FUSED softplus (each slab read exactly once chip-wide)
    {
        const float4* wm4 = reinterpret_cast<const float4*>(w_mu    + ((size_t)g * U + u0) * P);
        const float4* ws4 = reinterpret_cast<const float4*>(w_sigma + ((size_t)g * U + u0) * P);
        float4* swm = reinterpret_cast<float4*>(s_wmu);
        float4* ssp = reinterpret_cast<float4*>(s_sp);
        #pragma unroll
        for (int i = tid; i < UT * P / 4; i += 256) {
            swm[i] = wm4[i];
            float4 v = ws4[i];
            float4 r;
            r.x = softplus_f(SOFTPLUS_C + v.x);
            r.y = softplus_f(SOFTPLUS_C + v.y);
            r.z = softplus_f(SOFTPLUS_C + v.z);
            r.w = softplus_f(SOFTPLUS_C + v.w);
            ssp[i] = r;
        }
    }

    // per-unit bias constants (2 units per warp), computed by all lanes (cheap)
    float bmu_c[2], spb_c[2];
    #pragma unroll
    for (int t = 0; t < 2; t++) {
        int u = u0 + warp * 2 + t;
        bmu_c[t] = b_mu[g * U + u];
        spb_c[t] = softplus_f(SOFTPLUS_C + b_sigma[g * U + u]);
    }
    __syncthreads();

    if (start >= end) return;   // empty group: whole CTA exits together

    const float4* swm4 = reinterpret_cast<const float4*>(s_wmu);
    const float4* ssp4 = reinterpret_cast<const float4*>(s_sp);
    const int lu0 = warp * 2;
    const int lu1 = lu0 + 1;

    for (int idx = start; idx < end; ++idx) {
        const int buf  = (idx - start) & 1;
        const bool more = (idx + 1 < end);

        // issue next tile into the other buffer (released by last iter's end-barrier)
        if (more) {
            const int bn = g_items[idx + 1];
            const float4* src = reinterpret_cast<const float4*>(eps_w + ((size_t)bn * U + u0) * P);
            const uint32_t dst = s_eps_addr + (uint32_t)(buf ^ 1) * (UT * P * 4);
            #pragma unroll
            for (int i = tid; i < UT * P / 4; i += 256)
                cp_async16(dst + i * 16, src + i);
            cp_commit();
            cp_wait<1>();            // current tile (oldest group) is complete
        } else {
            cp_wait<0>();
        }
        __syncthreads();             // all threads' slices of the tile visible

        const int b = g_items[idx];
        const float4* sx4 = reinterpret_cast<const float4*>(x + (size_t)b * P);
        const float4* se4 = reinterpret_cast<const float4*>(s_eps) + buf * (UT * P / 4);

        float acc0 = 0.0f, acc1 = 0.0f;
        #pragma unroll
        for (int j = 0; j < 2; j++) {
            const int q = j * 32 + lane;       // float4 index within 256-wide row
            float4 xv = __ldg(&sx4[q]);        // L1-hit after first warp

            float4 e0 = se4[lu0 * 64 + q];
            float4 w0 = swm4[lu0 * 64 + q];
            float4 s0 = ssp4[lu0 * 64 + q];
            acc0 = fmaf(fmaf(s0.x, e0.x, w0.x), xv.x, acc0);
            acc0 = fmaf(fmaf(s0.y, e0.y, w0.y), xv.y, acc0);
            acc0 = fmaf(fmaf(s0.z, e0.z, w0.z), xv.z, acc0);
            acc0 = fmaf(fmaf(s0.w, e0.w, w0.w), xv.w, acc0);

            float4 e1 = se4[lu1 * 64 + q];
            float4 w1 = swm4[lu1 * 64 + q];
            float4 s1 = ssp4[lu1 * 64 + q];
            acc1 = fmaf(fmaf(s1.x, e1.x, w1.x), xv.x, acc1);
            acc1 = fmaf(fmaf(s1.y, e1.y, w1.y), xv.y, acc1);
            acc1 = fmaf(fmaf(s1.z, e1.z, w1.z), xv.z, acc1);
            acc1 = fmaf(fmaf(s1.w, e1.w, w1.w), xv.w, acc1);
        }

        // interleaved butterfly reductions (two independent chains overlap)
        #pragma unroll
        for (int o = 16; o; o >>= 1) {
            acc0 += __shfl_down_sync(0xffffffffu, acc0, o);
            acc1 += __shfl_down_sync(0xffffffffu, acc1, o);
        }
        if (lane == 0) {
            const int u = u0 + lu0;
            out[(size_t)b * U + u]     = acc0 + bmu_c[0] + spb_c[0] * eps_b[(size_t)b * U + u];
            out[(size_t)b * U + u + 1] = acc1 + bmu_c[1] + spb_c[1] * eps_b[(size_t)b * U + u + 1];
        }
        __syncthreads();             // release current buffer for the issue at idx+2
    }
}

// ---------------------------------------------------------------------------
// Launch
// Input order (metadata): x, gid, w_mu, w_sigma, b_mu, b_sigma, eps_w, eps_b
// ---------------------------------------------------------------------------
extern "C" void kernel_launch(void* const* d_in, const int* in_sizes, int n_in,
                              void* d_out, int out_size) {
    const float* x       = (const float*)d_in[0];
    const int*   gid     = (const int*)  d_in[1];
    const float* w_mu    = (const float*)d_in[2];
    const float* w_sigma = (const float*)d_in[3];
    const float* b_mu    = (const float*)d_in[4];
    const float* b_sigma = (const float*)d_in[5];
    const float* eps_w   = (const float*)d_in[6];
    const float* eps_b   = (const float*)d_in[7];
    float* out = (float*)d_out;

    // 1) bin batches by group
    bin_kernel<<<1, 256>>>(gid);

    // 2) main kernel (softplus fused into slab load; no precompute pass)
    const int shmem = (4096 + 4096 + 2 * 4096) * (int)sizeof(float);   // 64 KB
    cudaFuncSetAttribute(multilevel_dense_kernel,
                         cudaFuncAttributeMaxDynamicSharedMemorySize, shmem);
    dim3 grid(U / UT, G);   // (16, 64) = 1024 CTAs
    multilevel_dense_kernel<<<grid, 256, shmem>>>(x, w_mu, w_sigma, b_mu, b_sigma,
                                                  eps_w, eps_b, out);
}

// round 3
// speedup vs baseline: 1.4228x; 1.4228x over previous
#include <cuda_runtime.h>
#include <cstdint>

// Problem constants (fixed by the reference)
static constexpr int B  = 2048;   // batch
static constexpr int U  = 256;    // units
static constexpr int P  = 256;    // features
static constexpr int G  = 64;     // groups
static constexpr int UT = 16;     // unit tile per CTA
static constexpr int SPLIT = 2;   // intra-group batch split (gridDim.z)

#define SOFTPLUS_C 0.5413248546129181f

// Scratch (allocation-free rule: __device__ globals)
__device__ int g_items[B];        // batch indices sorted by group
__device__ int g_start[G + 1];    // group offsets into g_items

__device__ __forceinline__ float softplus_f(float v) {
    // numerically stable: max(v,0) + log1p(exp(-|v|)) (matches jax.nn.softplus f32)
    return fmaxf(v, 0.0f) + log1pf(expf(-fabsf(v)));
}

// ---------------------------------------------------------------------------
// Kernel 1: counting-sort batches by group (single block, tiny)
// ---------------------------------------------------------------------------
__global__ void bin_kernel(const int* __restrict__ gid) {
    __shared__ int cnt[G];
    __shared__ int off[G];
    int tid = threadIdx.x;
    if (tid < G) cnt[tid] = 0;
    __syncthreads();
    for (int b = tid; b < B; b += blockDim.x)
        atomicAdd(&cnt[gid[b]], 1);
    __syncthreads();
    if (tid == 0) {
        int s = 0;
        for (int g = 0; g < G; g++) {
            g_start[g] = s;
            off[g] = s;
            s += cnt[g];
        }
        g_start[G] = s;
    }
    __syncthreads();
    for (int b = tid; b < B; b += blockDim.x) {
        int g = gid[b];
        int pos = atomicAdd(&off[g], 1);
        g_items[pos] = b;   // intra-group order nondeterministic; outputs are
                            // per-batch independent -> results deterministic
    }
}

// ---------------------------------------------------------------------------
// Kernel 2: main kernel — barrier-free streaming.
// grid = (U/UT, G, SPLIT). CTA (ux, g, z) owns units [u0, u0+16) of group g
// and batches start+z, start+z+SPLIT, ... (load-balance split).
//  - w_mu + fused softplus(C+w_sigma) slabs in 32KB static SMEM (one barrier)
//  - each warp owns 2 units and FREE-RUNS over its batches: its eps rows are
//    private to it, x rows hit L1/L2, so NO __syncthreads in the loop.
//  - per iter: 4 eps LDG.128 + 8 LDS.128 + 2 x LDG.128 + 32 FFMA + 10 SHFL;
//    unroll lets the scoreboard overlap loads of iter i+1 with reduce of i.
// ---------------------------------------------------------------------------
__global__ __launch_bounds__(256) void multilevel_dense_kernel(
    const float* __restrict__ x,
    const float* __restrict__ w_mu,
    const float* __restrict__ w_sigma,
    const float* __restrict__ b_mu,
    const float* __restrict__ b_sigma,
    const float* __restrict__ eps_w,
    const float* __restrict__ eps_b,
    float* __restrict__ out)
{
    __shared__ float s_wmu[UT * P];   // 16 KB
    __shared__ float s_sp [UT * P];   // 16 KB

    const int g    = blockIdx.y;
    const int u0   = blockIdx.x * UT;
    const int z    = blockIdx.z;
    const int tid  = threadIdx.x;
    const int warp = tid >> 5;
    const int lane = tid & 31;

    // ---- weight slab load with FUSED softplus
    {
        const float4* wm4 = reinterpret_cast<const float4*>(w_mu    + ((size_t)g * U + u0) * P);
        const float4* ws4 = reinterpret_cast<const float4*>(w_sigma + ((size_t)g * U + u0) * P);
        float4* swm = reinterpret_cast<float4*>(s_wmu);
        float4* ssp = reinterpret_cast<float4*>(s_sp);
        #pragma unroll
        for (int i = tid; i < UT * P / 4; i += 256) {
            swm[i] = wm4[i];
            float4 v = ws4[i];
            float4 r;
            r.x = softplus_f(SOFTPLUS_C + v.x);
            r.y = softplus_f(SOFTPLUS_C + v.y);
            r.z = softplus_f(SOFTPLUS_C + v.z);
            r.w = softplus_f(SOFTPLUS_C + v.w);
            ssp[i] = r;
        }
    }

    // per-unit bias constants (2 units per warp), computed by all lanes (cheap)
    const int lu0 = warp * 2;
    const int lu1 = lu0 + 1;
    const float bmu0 = b_mu[g * U + u0 + lu0];
    const float bmu1 = b_mu[g * U + u0 + lu1];
    const float spb0 = softplus_f(SOFTPLUS_C + b_sigma[g * U + u0 + lu0]);
    const float spb1 = softplus_f(SOFTPLUS_C + b_sigma[g * U + u0 + lu1]);

    __syncthreads();   // slabs visible; LAST barrier in the kernel

    const int start = g_start[g];
    const int end   = g_start[g + 1];

    const float4* swm0 = reinterpret_cast<const float4*>(s_wmu) + lu0 * (P / 4);
    const float4* swm1 = reinterpret_cast<const float4*>(s_wmu) + lu1 * (P / 4);
    const float4* ssp0 = reinterpret_cast<const float4*>(s_sp)  + lu0 * (P / 4);
    const float4* ssp1 = reinterpret_cast<const float4*>(s_sp)  + lu1 * (P / 4);

    #pragma unroll 2
    for (int idx = start + z; idx < end; idx += SPLIT) {
        const int b = g_items[idx];
        const float4* xb = reinterpret_cast<const float4*>(x + (size_t)b * P);
        const float4* e0 = reinterpret_cast<const float4*>(eps_w + ((size_t)b * U + u0 + lu0) * P);
        const float4* e1 = reinterpret_cast<const float4*>(eps_w + ((size_t)b * U + u0 + lu1) * P);

        // issue all global loads up front (4 eps + 2 x per lane -> deep MLP)
        const int qa = lane;
        const int qb = lane + 32;
        float4 ea0 = e0[qa];
        float4 eb0 = e0[qb];
        float4 ea1 = e1[qa];
        float4 eb1 = e1[qb];
        float4 xa  = __ldg(&xb[qa]);
        float4 xb4 = __ldg(&xb[qb]);

        float4 wa0 = swm0[qa], sa0 = ssp0[qa];
        float4 wb0 = swm0[qb], sb0 = ssp0[qb];
        float4 wa1 = swm1[qa], sa1 = ssp1[qa];
        float4 wb1 = swm1[qb], sb1 = ssp1[qb];

        float acc0 = 0.0f, acc1 = 0.0f;
        acc0 = fmaf(fmaf(sa0.x, ea0.x, wa0.x), xa.x, acc0);
        acc0 = fmaf(fmaf(sa0.y, ea0.y, wa0.y), xa.y, acc0);
        acc0 = fmaf(fmaf(sa0.z, ea0.z, wa0.z), xa.z, acc0);
        acc0 = fmaf(fmaf(sa0.w, ea0.w, wa0.w), xa.w, acc0);
        acc0 = fmaf(fmaf(sb0.x, eb0.x, wb0.x), xb4.x, acc0);
        acc0 = fmaf(fmaf(sb0.y, eb0.y, wb0.y), xb4.y, acc0);
        acc0 = fmaf(fmaf(sb0.z, eb0.z, wb0.z), xb4.z, acc0);
        acc0 = fmaf(fmaf(sb0.w, eb0.w, wb0.w), xb4.w, acc0);

        acc1 = fmaf(fmaf(sa1.x, ea1.x, wa1.x), xa.x, acc1);
        acc1 = fmaf(fmaf(sa1.y, ea1.y, wa1.y), xa.y, acc1);
        acc1 = fmaf(fmaf(sa1.z, ea1.z, wa1.z), xa.z, acc1);
        acc1 = fmaf(fmaf(sa1.w, ea1.w, wa1.w), xa.w, acc1);
        acc1 = fmaf(fmaf(sb1.x, eb1.x, wb1.x), xb4.x, acc1);
        acc1 = fmaf(fmaf(sb1.y, eb1.y, wb1.y), xb4.y, acc1);
        acc1 = fmaf(fmaf(sb1.z, eb1.z, wb1.z), xb4.z, acc1);
        acc1 = fmaf(fmaf(sb1.w, eb1.w, wb1.w), xb4.w, acc1);

        // interleaved butterfly reductions (two independent chains)
        #pragma unroll
        for (int o = 16; o; o >>= 1) {
            acc0 += __shfl_down_sync(0xffffffffu, acc0, o);
            acc1 += __shfl_down_sync(0xffffffffu, acc1, o);
        }
        if (lane == 0) {
            const size_t ob = (size_t)b * U + u0 + lu0;
            float2 r;
            r.x = acc0 + bmu0 + spb0 * eps_b[ob];
            r.y = acc1 + bmu1 + spb1 * eps_b[ob + 1];
            *reinterpret_cast<float2*>(out + ob) = r;
        }
    }
}

// ---------------------------------------------------------------------------
// Launch
// Input order (metadata): x, gid, w_mu, w_sigma, b_mu, b_sigma, eps_w, eps_b
// ---------------------------------------------------------------------------
extern "C" void kernel_launch(void* const* d_in, const int* in_sizes, int n_in,
                              void* d_out, int out_size) {
    const float* x       = (const float*)d_in[0];
    const int*   gid     = (const int*)  d_in[1];
    const float* w_mu    = (const float*)d_in[2];
    const float* w_sigma = (const float*)d_in[3];
    const float* b_mu    = (const float*)d_in[4];
    const float* b_sigma = (const float*)d_in[5];
    const float* eps_w   = (const float*)d_in[6];
    const float* eps_b   = (const float*)d_in[7];
    float* out = (float*)d_out;

    // 1) bin batches by group
    bin_kernel<<<1, 256>>>(gid);

    // 2) main kernel (static 32KB smem; no in-loop barriers)
    dim3 grid(U / UT, G, SPLIT);   // (16, 64, 2) = 2048 CTAs
    multilevel_dense_kernel<<<grid, 256>>>(x, w_mu, w_sigma, b_mu, b_sigma,
                                           eps_w, eps_b, out);
}

// round 5
// speedup vs baseline: 1.4984x; 1.0531x over previous
#include <cuda_runtime.h>
#include <cstdint>

// Problem constants (fixed by the reference)
static constexpr int B  = 2048;   // batch
static constexpr int U  = 256;    // units
static constexpr int P  = 256;    // features
static constexpr int G  = 64;     // groups
static constexpr int UT = 8;      // units per CTA (1 per warp)
static constexpr int SPLIT = 2;   // intra-group batch split (gridDim.z)

#define SOFTPLUS_C 0.5413248546129181f

// Scratch (allocation-free rule: __device__ globals)
__device__ int g_items[B];        // batch indices sorted by group
__device__ int g_start[G + 1];    // group offsets into g_items

__device__ __forceinline__ float softplus_f(float v) {
    // numerically stable: max(v,0) + log1p(exp(-|v|)) (matches jax.nn.softplus f32)
    return fmaxf(v, 0.0f) + log1pf(expf(-fabsf(v)));
}

// warp sum: 5-step butterfly (sm_103 has NO redux.f32 — integer redux only)
__device__ __forceinline__ float warp_sum(float v) {
    #pragma unroll
    for (int o = 16; o; o >>= 1) v += __shfl_xor_sync(0xffffffffu, v, o);
    return v;
}

// ---------------------------------------------------------------------------
// Kernel 1: counting-sort batches by group (single block, tiny)
// ---------------------------------------------------------------------------
__global__ void bin_kernel(const int* __restrict__ gid) {
    __shared__ int cnt[G];
    __shared__ int off[G];
    int tid = threadIdx.x;
    if (tid < G) cnt[tid] = 0;
    __syncthreads();
    for (int b = tid; b < B; b += blockDim.x)
        atomicAdd(&cnt[gid[b]], 1);
    __syncthreads();
    if (tid == 0) {
        int s = 0;
        for (int g = 0; g < G; g++) {
            g_start[g] = s;
            off[g] = s;
            s += cnt[g];
        }
        g_start[G] = s;
    }
    __syncthreads();
    for (int b = tid; b < B; b += blockDim.x) {
        int g = gid[b];
        int pos = atomicAdd(&off[g], 1);
        g_items[pos] = b;   // intra-group order nondeterministic; outputs are
                            // per-batch independent -> results deterministic
    }
}

// ---------------------------------------------------------------------------
// Kernel 2: main kernel — zero-barrier, register-resident weights,
// SOFTWARE-PIPELINED across batches (depth 2).
// grid = (U/UT, G, SPLIT). Warp w of CTA (ux, g, z) owns unit u = ux*8 + w
// of group g and free-runs over batches start+z, start+z+SPLIT, ...
// Per stage: issue next batch's 4 LDG.128 (+eps_b) FIRST, then FMA+reduce
// the current batch — the shuffle tail overlaps the next batch's DRAM fetch.
// ---------------------------------------------------------------------------
__global__ __launch_bounds__(256) void multilevel_dense_kernel(
    const float* __restrict__ x,
    const float* __restrict__ w_mu,
    const float* __restrict__ w_sigma,
    const float* __restrict__ b_mu,
    const float* __restrict__ b_sigma,
    const float* __restrict__ eps_w,
    const float* __restrict__ eps_b,
    float* __restrict__ out)
{
    const int g    = blockIdx.y;
    const int z    = blockIdx.z;
    const int warp = threadIdx.x >> 5;
    const int lane = threadIdx.x & 31;
    const int u    = blockIdx.x * UT + warp;

    // ---- persistent per-lane weights: features [lane*4..+4) and [128+lane*4..+4)
    float4 wA, wB, sA, sB;
    {
        const float4* wm4 = reinterpret_cast<const float4*>(w_mu    + ((size_t)g * U + u) * P);
        const float4* ws4 = reinterpret_cast<const float4*>(w_sigma + ((size_t)g * U + u) * P);
        wA = wm4[lane];
        wB = wm4[lane + 32];
        float4 vA = ws4[lane];
        float4 vB = ws4[lane + 32];
        sA.x = softplus_f(SOFTPLUS_C + vA.x);
        sA.y = softplus_f(SOFTPLUS_C + vA.y);
        sA.z = softplus_f(SOFTPLUS_C + vA.z);
        sA.w = softplus_f(SOFTPLUS_C + vA.w);
        sB.x = softplus_f(SOFTPLUS_C + vB.x);
        sB.y = softplus_f(SOFTPLUS_C + vB.y);
        sB.z = softplus_f(SOFTPLUS_C + vB.z);
        sB.w = softplus_f(SOFTPLUS_C + vB.w);
    }
    const float bmu = b_mu[g * U + u];
    const float spb = softplus_f(SOFTPLUS_C + b_sigma[g * U + u]);

    const int end = g_start[g + 1];
    int i = g_start[g] + z;
    if (i >= end) return;

    // ---- prologue: issue loads for the first batch
    int b_cur = g_items[i];
    float4 cEa, cEb, cXa, cXb;
    float  cEps;
    {
        const float4* e = reinterpret_cast<const float4*>(eps_w + ((size_t)b_cur * U + u) * P);
        const float4* xv = reinterpret_cast<const float4*>(x + (size_t)b_cur * P);
        cEa = __ldcs(&e[lane]);
        cEb = __ldcs(&e[lane + 32]);
        cXa = __ldg(&xv[lane]);
        cXb = __ldg(&xv[lane + 32]);
        cEps = __ldg(&eps_b[(size_t)b_cur * U + u]);   // warp-uniform -> broadcast
    }

    #pragma unroll 2
    while (true) {
        const int inext = i + SPLIT;
        const bool more = inext < end;

        // ---- stage A: issue NEXT batch's loads (overlap current's compute+reduce)
        int b_nxt = 0;
        float4 nEa, nEb, nXa, nXb;
        float  nEps = 0.0f;
        if (more) {
            b_nxt = g_items[inext];
            const float4* e = reinterpret_cast<const float4*>(eps_w + ((size_t)b_nxt * U + u) * P);
            const float4* xv = reinterpret_cast<const float4*>(x + (size_t)b_nxt * P);
            nEa = __ldcs(&e[lane]);
            nEb = __ldcs(&e[lane + 32]);
            nXa = __ldg(&xv[lane]);
            nXb = __ldg(&xv[lane + 32]);
            nEps = __ldg(&eps_b[(size_t)b_nxt * U + u]);
        }

        // ---- stage B: compute current batch
        float acc = 0.0f;
        acc = fmaf(fmaf(sA.x, cEa.x, wA.x), cXa.x, acc);
        acc = fmaf(fmaf(sA.y, cEa.y, wA.y), cXa.y, acc);
        acc = fmaf(fmaf(sA.z, cEa.z, wA.z), cXa.z, acc);
        acc = fmaf(fmaf(sA.w, cEa.w, wA.w), cXa.w, acc);
        acc = fmaf(fmaf(sB.x, cEb.x, wB.x), cXb.x, acc);
        acc = fmaf(fmaf(sB.y, cEb.y, wB.y), cXb.y, acc);
        acc = fmaf(fmaf(sB.z, cEb.z, wB.z), cXb.z, acc);
        acc = fmaf(fmaf(sB.w, cEb.w, wB.w), cXb.w, acc);

        acc = warp_sum(acc);   // next batch's DRAM fetch in flight during this tail

        if (lane == 0)
            out[(size_t)b_cur * U + u] = acc + bmu + spb * cEps;

        if (!more) break;

        // ---- rotate buffers (register renaming after unroll removes the moves)
        i = inext;
        b_cur = b_nxt;
        cEa = nEa; cEb = nEb; cXa = nXa; cXb = nXb; cEps = nEps;
    }
}

// ---------------------------------------------------------------------------
// Launch
// Input order (metadata): x, gid, w_mu, w_sigma, b_mu, b_sigma, eps_w, eps_b
// ---------------------------------------------------------------------------
extern "C" void kernel_launch(void* const* d_in, const int* in_sizes, int n_in,
                              void* d_out, int out_size) {
    const float* x       = (const float*)d_in[0];
    const int*   gid     = (const int*)  d_in[1];
    const float* w_mu    = (const float*)d_in[2];
    const float* w_sigma = (const float*)d_in[3];
    const float* b_mu    = (const float*)d_in[4];
    const float* b_sigma = (const float*)d_in[5];
    const float* eps_w   = (const float*)d_in[6];
    const float* eps_b   = (const float*)d_in[7];
    float* out = (float*)d_out;

    // 1) bin batches by group
    bin_kernel<<<1, 256>>>(gid);

    // 2) main kernel (no smem, no barriers; weights register-resident; pipelined)
    dim3 grid(U / UT, G, SPLIT);   // (32, 64, 2) = 4096 CTAs
    multilevel_dense_kernel<<<grid, 256>>>(x, w_mu, w_sigma, b_mu, b_sigma,
                                           eps_w, eps_b, out);
}